// round 5
// baseline (speedup 1.0000x reference)
#include <cuda_runtime.h>

#define NVOX    150000
#define CIN     32
#define COUT    64
#define KCENTER 13
#define NWARPS  8                      // warps per block
#define NBLK    586                    // 586*8*32 = 150016 >= NVOX; <= 148*4 resident

__device__ float    g_stats[2*COUT];   // zero-init at load; reset by last block each run
__device__ unsigned g_bar;             // grid barrier counter
__device__ unsigned g_done;            // completion counter for reset

// ---------------------------------------------------------------- f32x2 helpers
__device__ __forceinline__ unsigned long long dup2(float x) {
    unsigned long long r; asm("mov.b64 %0, {%1, %1};" : "=l"(r) : "f"(x)); return r;
}
__device__ __forceinline__ unsigned long long pack2(float x, float y) {
    unsigned long long r; asm("mov.b64 %0, {%1, %2};" : "=l"(r) : "f"(x), "f"(y)); return r;
}
__device__ __forceinline__ void unpack2(unsigned long long v, float& x, float& y) {
    asm("mov.b64 {%0, %1}, %2;" : "=f"(x), "=f"(y) : "l"(v));
}
__device__ __forceinline__ void ffma2(unsigned long long& acc,
                                      unsigned long long a, unsigned long long b) {
    asm("fma.rn.f32x2 %0, %1, %2, %0;" : "+l"(acc) : "l"(a), "l"(b));
}
__device__ __forceinline__ unsigned long long add2(unsigned long long a, unsigned long long b) {
    unsigned long long r; asm("add.rn.f32x2 %0, %1, %2;" : "=l"(r) : "l"(a), "l"(b)); return r;
}

// ================================================================ fused kernel
__global__ __launch_bounds__(32*NWARPS, 4)
void fused_kernel(const float* __restrict__ features,
                  const float* __restrict__ weight,
                  const float* __restrict__ gamma,
                  const float* __restrict__ beta,
                  const int*   __restrict__ nbr,
                  float* __restrict__ out)
{
    const int tid  = threadIdx.x;
    const int lane = tid & 31;
    const int warp = tid >> 5;
    const int d0   = lane * 2;

    __shared__ float4 red[32*NWARPS];
    __shared__ float  sc[COUT], sh[COUT];

    // ---------------- phase 1: conv + local stats ----------------
    const int chunk = blockIdx.x * NWARPS + warp;    // 0..4687
    const int n0    = chunk * 32;

    // validity mask of the 26 non-center offsets for this lane's voxel
    unsigned m = 0;
    {
        const int  nl   = n0 + lane;
        const bool live = nl < NVOX;
        #pragma unroll
        for (int j = 0; j < 26; j++) {
            int k = j + (j >= KCENTER);
            int v = live ? __ldg(&nbr[k*NVOX + nl]) : -1;
            m |= (v >= 0) ? (1u << j) : 0u;
        }
    }

    // center weights in registers: W13[c][d0:d0+2]
    unsigned long long w[CIN];
    {
        const float* wk = weight + KCENTER*CIN*COUT;
        #pragma unroll
        for (int c = 0; c < CIN; c++) {
            float2 wv = __ldg((const float2*)(wk + c*COUT + d0));
            w[c] = pack2(wv.x, wv.y);
        }
    }

    unsigned long long s = 0ull, q = 0ull;   // packed (d0,d0+1) sum / sumsq
    const int nv = (n0 < NVOX) ? min(32, NVOX - n0) : 0;

    for (int i = 0; i < nv; i++) {
        const int n = n0 + i;
        unsigned mi = __shfl_sync(0xffffffffu, m, i);

        const float4* f4 = (const float4*)(features + (size_t)n * CIN);
        unsigned long long accA = 0ull, accB = 0ull;
        #pragma unroll
        for (int j = 0; j < 8; j++) {
            float4 v = f4[j];                  // broadcast LDG.128
            ffma2(accA, dup2(v.x), w[4*j+0]);
            ffma2(accB, dup2(v.y), w[4*j+1]);
            ffma2(accA, dup2(v.z), w[4*j+2]);
            ffma2(accB, dup2(v.w), w[4*j+3]);
        }

        while (mi) {                           // rare extras (~0.23/voxel)
            int j = __ffs(mi) - 1; mi &= mi - 1;
            int k = j + (j >= KCENTER);
            int idx = __ldg(&nbr[k*NVOX + n]);                 // L1-hot
            const float* wk = weight + k*CIN*COUT;
            const float4* g4 = (const float4*)(features + (size_t)idx * CIN);
            #pragma unroll
            for (int jj = 0; jj < 8; jj++) {
                float4 v  = g4[jj];
                float2 w0 = __ldg((const float2*)(wk + (4*jj+0)*COUT + d0));
                float2 w1 = __ldg((const float2*)(wk + (4*jj+1)*COUT + d0));
                float2 w2 = __ldg((const float2*)(wk + (4*jj+2)*COUT + d0));
                float2 w3 = __ldg((const float2*)(wk + (4*jj+3)*COUT + d0));
                ffma2(accA, dup2(v.x), pack2(w0.x, w0.y));
                ffma2(accB, dup2(v.y), pack2(w1.x, w1.y));
                ffma2(accA, dup2(v.z), pack2(w2.x, w2.y));
                ffma2(accB, dup2(v.w), pack2(w3.x, w3.y));
            }
        }

        unsigned long long acc = add2(accA, accB);
        float a0, a1; unpack2(acc, a0, a1);
        *(float2*)(out + (size_t)n*COUT + d0) = make_float2(a0, a1);

        s = add2(s, acc);
        ffma2(q, acc, acc);
    }

    // block reduce per-lane packed stats
    {
        float s0, s1, q0, q1;
        unpack2(s, s0, s1); unpack2(q, q0, q1);
        red[warp*32 + lane] = make_float4(s0, s1, q0, q1);
    }
    __syncthreads();
    if (tid < 32) {
        float4 a = red[tid];
        #pragma unroll
        for (int ww = 1; ww < NWARPS; ww++) {
            float4 b = red[ww*32 + tid];
            a.x += b.x; a.y += b.y; a.z += b.z; a.w += b.w;
        }
        atomicAdd(&g_stats[2*tid + 0],        a.x);
        atomicAdd(&g_stats[2*tid + 1],        a.y);
        atomicAdd(&g_stats[COUT + 2*tid + 0], a.z);
        atomicAdd(&g_stats[COUT + 2*tid + 1], a.w);
    }

    // ---------------- grid barrier (all blocks wave-1 resident) ----------------
    __threadfence();
    __syncthreads();
    if (tid == 0) {
        atomicAdd(&g_bar, 1u);
        while (*(volatile unsigned*)&g_bar < (unsigned)gridDim.x) __nanosleep(64);
    }
    __syncthreads();
    __threadfence();

    // ---------------- phase 2: finalize + normalize ----------------
    if (tid < COUT) {
        float inv_n = 1.0f / (float)NVOX;
        float mean  = g_stats[tid] * inv_n;
        float var   = g_stats[COUT + tid] * inv_n - mean*mean;
        float inv   = rsqrtf(var + 1e-5f);
        float scl   = gamma[tid] * inv;
        sc[tid] = scl;
        sh[tid] = beta[tid] - mean*scl;
    }
    __syncthreads();

    const int total4 = NVOX*COUT/4;           // 2,400,000
    float4* o4 = (float4*)out;
    for (int i = blockIdx.x*blockDim.x + tid; i < total4; i += gridDim.x*blockDim.x) {
        float4 v = o4[i];                      // L2-hot (written above)
        int bd = (i*4) & (COUT-1);
        v.x = fmaxf(fmaf(v.x, sc[bd+0], sh[bd+0]), 0.f);
        v.y = fmaxf(fmaf(v.y, sc[bd+1], sh[bd+1]), 0.f);
        v.z = fmaxf(fmaf(v.z, sc[bd+2], sh[bd+2]), 0.f);
        v.w = fmaxf(fmaf(v.w, sc[bd+3], sh[bd+3]), 0.f);
        o4[i] = v;
    }

    // ---------------- reset globals for next (graph-replayed) run ----------------
    __syncthreads();
    if (tid == 0) {
        unsigned d = atomicAdd(&g_done, 1u);
        if (d == (unsigned)gridDim.x - 1u) {   // last block resets everything
            #pragma unroll
            for (int i = 0; i < 2*COUT; i++) g_stats[i] = 0.f;
            __threadfence();
            g_bar  = 0u;
            g_done = 0u;
            __threadfence();
        }
    }
}

// ---------------------------------------------------------------- launch
extern "C" void kernel_launch(void* const* d_in, const int* in_sizes, int n_in,
                              void* d_out, int out_size)
{
    const float* features = (const float*)d_in[0];  // [150000,32]
    const float* weight   = (const float*)d_in[1];  // [27,32,64]
    const float* gamma    = (const float*)d_in[2];  // [64]
    const float* beta     = (const float*)d_in[3];  // [64]
    const int*   nbr      = (const int*)  d_in[4];  // [27,150000]
    float* out = (float*)d_out;                     // [150000,64]

    fused_kernel<<<NBLK, 32*NWARPS>>>(features, weight, gamma, beta, nbr, out);
}

// round 6
// speedup vs baseline: 1.8294x; 1.8294x over previous
#include <cuda_runtime.h>

#define NVOX    150000
#define CIN     32
#define COUT    64
#define KCENTER 13
#define NWARPS  8
#define NBLK    296                    // 148 SM x 2 resident blocks -> all wave-1
#define NCHUNK  ((NVOX + 31) / 32)     // 4688

__device__ float    g_stats[2*COUT];   // zero at load; reset by last block each run
__device__ unsigned g_bar;
__device__ unsigned g_done;

// ---------------------------------------------------------------- f32x2 helpers
__device__ __forceinline__ unsigned long long dup2(float x) {
    unsigned long long r; asm("mov.b64 %0, {%1, %1};" : "=l"(r) : "f"(x)); return r;
}
__device__ __forceinline__ unsigned long long pack2(float x, float y) {
    unsigned long long r; asm("mov.b64 %0, {%1, %2};" : "=l"(r) : "f"(x), "f"(y)); return r;
}
__device__ __forceinline__ void unpack2(unsigned long long v, float& x, float& y) {
    asm("mov.b64 {%0, %1}, %2;" : "=f"(x), "=f"(y) : "l"(v));
}
__device__ __forceinline__ void ffma2(unsigned long long& acc,
                                      unsigned long long a, unsigned long long b) {
    asm("fma.rn.f32x2 %0, %1, %2, %0;" : "+l"(acc) : "l"(a), "l"(b));
}
__device__ __forceinline__ unsigned long long add2(unsigned long long a, unsigned long long b) {
    unsigned long long r; asm("add.rn.f32x2 %0, %1, %2;" : "=l"(r) : "l"(a), "l"(b)); return r;
}

// ================================================================ fused kernel
__global__ __launch_bounds__(32*NWARPS, 2)   // 128 regs/thread: weights stay in RF
void fused_kernel(const float* __restrict__ features,
                  const float* __restrict__ weight,
                  const float* __restrict__ gamma,
                  const float* __restrict__ beta,
                  const int*   __restrict__ nbr,
                  float* __restrict__ out)
{
    const int tid  = threadIdx.x;
    const int lane = tid & 31;
    const int warp = tid >> 5;
    const int d0   = lane * 2;

    __shared__ float4 red[32*NWARPS];
    __shared__ float  sc[COUT], sh[COUT];

    // center weights in registers: W13[c][d0:d0+2]  (64 regs)
    unsigned long long w[CIN];
    {
        const float* wk = weight + KCENTER*CIN*COUT;
        #pragma unroll
        for (int c = 0; c < CIN; c++) {
            float2 wv = __ldg((const float2*)(wk + c*COUT + d0));
            w[c] = pack2(wv.x, wv.y);
        }
    }

    unsigned long long s = 0ull, q = 0ull;   // packed (d0,d0+1) sum / sumsq

    // ---------------- phase 1: conv + local stats (2 chunks per warp) --------
    const int wid0   = blockIdx.x * NWARPS + warp;
    const int wtotal = NBLK * NWARPS;                 // 2368

    for (int chunk = wid0; chunk < NCHUNK; chunk += wtotal) {
        const int n0 = chunk * 32;

        // validity mask of the 26 non-center offsets for this lane's voxel
        unsigned m = 0;
        {
            const int  nl   = n0 + lane;
            const bool live = nl < NVOX;
            #pragma unroll
            for (int j = 0; j < 26; j++) {
                int k = j + (j >= KCENTER);
                int v = live ? __ldg(&nbr[k*NVOX + nl]) : -1;
                m |= (v >= 0) ? (1u << j) : 0u;
            }
        }

        const int nv = (n0 < NVOX) ? min(32, NVOX - n0) : 0;
        for (int i = 0; i < nv; i++) {
            const int n = n0 + i;
            unsigned mi = __shfl_sync(0xffffffffu, m, i);

            const float4* f4 = (const float4*)(features + (size_t)n * CIN);
            unsigned long long accA = 0ull, accB = 0ull;
            #pragma unroll
            for (int j = 0; j < 8; j++) {
                float4 v = f4[j];                  // broadcast LDG.128
                ffma2(accA, dup2(v.x), w[4*j+0]);
                ffma2(accB, dup2(v.y), w[4*j+1]);
                ffma2(accA, dup2(v.z), w[4*j+2]);
                ffma2(accB, dup2(v.w), w[4*j+3]);
            }

            while (mi) {                           // rare extras (~0.23/voxel)
                int j = __ffs(mi) - 1; mi &= mi - 1;
                int k = j + (j >= KCENTER);
                int idx = __ldg(&nbr[k*NVOX + n]);             // L1-hot
                const float* wk = weight + k*CIN*COUT;
                const float4* g4 = (const float4*)(features + (size_t)idx * CIN);
                #pragma unroll
                for (int jj = 0; jj < 8; jj++) {
                    float4 v  = g4[jj];
                    float2 w0 = __ldg((const float2*)(wk + (4*jj+0)*COUT + d0));
                    float2 w1 = __ldg((const float2*)(wk + (4*jj+1)*COUT + d0));
                    float2 w2 = __ldg((const float2*)(wk + (4*jj+2)*COUT + d0));
                    float2 w3 = __ldg((const float2*)(wk + (4*jj+3)*COUT + d0));
                    ffma2(accA, dup2(v.x), pack2(w0.x, w0.y));
                    ffma2(accB, dup2(v.y), pack2(w1.x, w1.y));
                    ffma2(accA, dup2(v.z), pack2(w2.x, w2.y));
                    ffma2(accB, dup2(v.w), pack2(w3.x, w3.y));
                }
            }

            unsigned long long acc = add2(accA, accB);
            float a0, a1; unpack2(acc, a0, a1);
            *(float2*)(out + (size_t)n*COUT + d0) = make_float2(a0, a1);

            s = add2(s, acc);
            ffma2(q, acc, acc);
        }
    }

    // block reduce per-lane packed stats
    {
        float s0, s1, q0, q1;
        unpack2(s, s0, s1); unpack2(q, q0, q1);
        red[warp*32 + lane] = make_float4(s0, s1, q0, q1);
    }
    __syncthreads();
    if (tid < 32) {
        float4 a = red[tid];
        #pragma unroll
        for (int ww = 1; ww < NWARPS; ww++) {
            float4 b = red[ww*32 + tid];
            a.x += b.x; a.y += b.y; a.z += b.z; a.w += b.w;
        }
        atomicAdd(&g_stats[2*tid + 0],        a.x);
        atomicAdd(&g_stats[2*tid + 1],        a.y);
        atomicAdd(&g_stats[COUT + 2*tid + 0], a.z);
        atomicAdd(&g_stats[COUT + 2*tid + 1], a.w);
    }

    // ---------------- grid barrier (all 296 blocks resident) -----------------
    __threadfence();
    __syncthreads();
    if (tid == 0) {
        atomicAdd(&g_bar, 1u);
        while (*(volatile unsigned*)&g_bar < (unsigned)gridDim.x) __nanosleep(64);
    }
    __syncthreads();
    __threadfence();

    // ---------------- phase 2: finalize + normalize --------------------------
    if (tid < COUT) {
        float inv_n = 1.0f / (float)NVOX;
        float mean  = g_stats[tid] * inv_n;
        float var   = g_stats[COUT + tid] * inv_n - mean*mean;
        float inv   = rsqrtf(var + 1e-5f);
        float scl   = gamma[tid] * inv;
        sc[tid] = scl;
        sh[tid] = beta[tid] - mean*scl;
    }
    __syncthreads();

    const int total4 = NVOX*COUT/4;           // 2,400,000
    float4* o4 = (float4*)out;
    for (int i = blockIdx.x*blockDim.x + tid; i < total4; i += gridDim.x*blockDim.x) {
        float4 v = o4[i];                      // L2-hot (written in phase 1)
        int bd = (i*4) & (COUT-1);
        v.x = fmaxf(fmaf(v.x, sc[bd+0], sh[bd+0]), 0.f);
        v.y = fmaxf(fmaf(v.y, sc[bd+1], sh[bd+1]), 0.f);
        v.z = fmaxf(fmaf(v.z, sc[bd+2], sh[bd+2]), 0.f);
        v.w = fmaxf(fmaf(v.w, sc[bd+3], sh[bd+3]), 0.f);
        o4[i] = v;
    }

    // ---------------- reset globals for next graph replay --------------------
    __syncthreads();
    if (tid == 0) {
        unsigned d = atomicAdd(&g_done, 1u);
        if (d == (unsigned)gridDim.x - 1u) {
            #pragma unroll
            for (int i = 0; i < 2*COUT; i++) g_stats[i] = 0.f;
            __threadfence();
            g_bar  = 0u;
            g_done = 0u;
            __threadfence();
        }
    }
}

// ---------------------------------------------------------------- launch
extern "C" void kernel_launch(void* const* d_in, const int* in_sizes, int n_in,
                              void* d_out, int out_size)
{
    const float* features = (const float*)d_in[0];  // [150000,32]
    const float* weight   = (const float*)d_in[1];  // [27,32,64]
    const float* gamma    = (const float*)d_in[2];  // [64]
    const float* beta     = (const float*)d_in[3];  // [64]
    const int*   nbr      = (const int*)  d_in[4];  // [27,150000]
    float* out = (float*)d_out;                     // [150000,64]

    fused_kernel<<<NBLK, 32*NWARPS>>>(features, weight, gamma, beta, nbr, out);
}

// round 7
// speedup vs baseline: 1.9444x; 1.0629x over previous
#include <cuda_runtime.h>

#define NVOX    150000
#define CIN     32
#define COUT    64
#define KCENTER 13
#define NWARPS  8
#define NBLK    296                    // 148 SM x 2 resident -> whole grid wave-1
#define NCHUNK  ((NVOX + 31) / 32)     // 4688

__device__ float    g_stats[2*COUT];   // zero at load; reset by last block each run
__device__ unsigned g_bar;
__device__ unsigned g_done;

// ---------------------------------------------------------------- f32x2 helpers
__device__ __forceinline__ unsigned long long dup2(float x) {
    unsigned long long r; asm("mov.b64 %0, {%1, %1};" : "=l"(r) : "f"(x)); return r;
}
__device__ __forceinline__ unsigned long long pack2(float x, float y) {
    unsigned long long r; asm("mov.b64 %0, {%1, %2};" : "=l"(r) : "f"(x), "f"(y)); return r;
}
__device__ __forceinline__ void unpack2(unsigned long long v, float& x, float& y) {
    asm("mov.b64 {%0, %1}, %2;" : "=f"(x), "=f"(y) : "l"(v));
}
__device__ __forceinline__ void ffma2(unsigned long long& acc,
                                      unsigned long long a, unsigned long long b) {
    asm("fma.rn.f32x2 %0, %1, %2, %0;" : "+l"(acc) : "l"(a), "l"(b));
}
__device__ __forceinline__ unsigned long long add2(unsigned long long a, unsigned long long b) {
    unsigned long long r; asm("add.rn.f32x2 %0, %1, %2;" : "=l"(r) : "l"(a), "l"(b)); return r;
}

// ================================================================ fused kernel
__global__ __launch_bounds__(32*NWARPS, 2)   // 128 regs/thread
void fused_kernel(const float* __restrict__ features,
                  const float* __restrict__ weight,
                  const float* __restrict__ gamma,
                  const float* __restrict__ beta,
                  const int*   __restrict__ nbr,
                  float* __restrict__ out)
{
    const int tid  = threadIdx.x;
    const int lane = tid & 31;
    const int warp = tid >> 5;
    const int d0   = lane * 2;

    __shared__ float4 sF[NWARPS][32*8];    // 4 KB/warp feature staging (32 rows)
    __shared__ float4 red[32*NWARPS];
    __shared__ float  sc[COUT], sh[COUT];

    // center weights in registers: W13[c][d0:d0+2]  (64 regs)
    unsigned long long w[CIN];
    {
        const float* wk = weight + KCENTER*CIN*COUT;
        #pragma unroll
        for (int c = 0; c < CIN; c++) {
            float2 wv = __ldg((const float2*)(wk + c*COUT + d0));
            w[c] = pack2(wv.x, wv.y);
        }
    }

    unsigned long long s = 0ull, q = 0ull;   // packed (d0,d0+1) sum / sumsq

    // ---------------- phase 1: conv + local stats ----------------------------
    const int wid0   = blockIdx.x * NWARPS + warp;
    const int wtotal = NBLK * NWARPS;                 // 2368

    for (int chunk = wid0; chunk < NCHUNK; chunk += wtotal) {
        const int n0 = chunk * 32;

        // bulk-stage 32 feature rows into smem: 8 coalesced LDG.128 (512B each)
        {
            const float4* src = (const float4*)(features + (size_t)n0 * CIN);
            #pragma unroll
            for (int j = 0; j < 8; j++) {
                int elem = j*32 + lane;        // float4 index; 8 per row
                int row  = elem >> 3;
                if (n0 + row < NVOX) sF[warp][elem] = src[elem];
            }
        }

        // validity mask of the 26 non-center offsets (coalesced per k)
        unsigned m = 0;
        {
            const int  nl   = n0 + lane;
            const bool live = nl < NVOX;
            #pragma unroll
            for (int j = 0; j < 26; j++) {
                int k = j + (j >= KCENTER);
                int v = live ? __ldg(&nbr[k*NVOX + nl]) : -1;
                m |= (v >= 0) ? (1u << j) : 0u;
            }
        }
        __syncwarp();

        const int nv = (n0 < NVOX) ? min(32, NVOX - n0) : 0;
        for (int i = 0; i < nv; i++) {
            const int n = n0 + i;
            unsigned mi = __shfl_sync(0xffffffffu, m, i);

            const float4* fr = &sF[warp][i*8];   // this voxel's row (smem)
            unsigned long long accA = 0ull, accB = 0ull;
            #pragma unroll
            for (int j = 0; j < 8; j++) {
                float4 v = fr[j];                // LDS.128 broadcast, 29cyc
                ffma2(accA, dup2(v.x), w[4*j+0]);
                ffma2(accB, dup2(v.y), w[4*j+1]);
                ffma2(accA, dup2(v.z), w[4*j+2]);
                ffma2(accB, dup2(v.w), w[4*j+3]);
            }

            while (mi) {                         // rare extras (~0.23/voxel)
                int j = __ffs(mi) - 1; mi &= mi - 1;
                int k = j + (j >= KCENTER);
                int idx = __ldg(&nbr[k*NVOX + n]);              // L1-hot
                const float* wk = weight + k*CIN*COUT;
                const float4* g4 = (const float4*)(features + (size_t)idx * CIN);
                #pragma unroll
                for (int jj = 0; jj < 8; jj++) {
                    float4 v  = g4[jj];
                    float2 w0 = __ldg((const float2*)(wk + (4*jj+0)*COUT + d0));
                    float2 w1 = __ldg((const float2*)(wk + (4*jj+1)*COUT + d0));
                    float2 w2 = __ldg((const float2*)(wk + (4*jj+2)*COUT + d0));
                    float2 w3 = __ldg((const float2*)(wk + (4*jj+3)*COUT + d0));
                    ffma2(accA, dup2(v.x), pack2(w0.x, w0.y));
                    ffma2(accB, dup2(v.y), pack2(w1.x, w1.y));
                    ffma2(accA, dup2(v.z), pack2(w2.x, w2.y));
                    ffma2(accB, dup2(v.w), pack2(w3.x, w3.y));
                }
            }

            unsigned long long acc = add2(accA, accB);
            float a0, a1; unpack2(acc, a0, a1);
            *(float2*)(out + (size_t)n*COUT + d0) = make_float2(a0, a1);

            s = add2(s, acc);
            ffma2(q, acc, acc);
        }
        __syncwarp();   // protect sF before next chunk overwrites
    }

    // block reduce per-lane packed stats
    {
        float s0, s1, q0, q1;
        unpack2(s, s0, s1); unpack2(q, q0, q1);
        red[warp*32 + lane] = make_float4(s0, s1, q0, q1);
    }
    __syncthreads();
    if (tid < 32) {
        float4 a = red[tid];
        #pragma unroll
        for (int ww = 1; ww < NWARPS; ww++) {
            float4 b = red[ww*32 + tid];
            a.x += b.x; a.y += b.y; a.z += b.z; a.w += b.w;
        }
        atomicAdd(&g_stats[2*tid + 0],        a.x);
        atomicAdd(&g_stats[2*tid + 1],        a.y);
        atomicAdd(&g_stats[COUT + 2*tid + 0], a.z);
        atomicAdd(&g_stats[COUT + 2*tid + 1], a.w);
    }

    // ---------------- grid barrier (all 296 blocks resident) -----------------
    __threadfence();
    __syncthreads();
    if (tid == 0) {
        atomicAdd(&g_bar, 1u);
        while (*(volatile unsigned*)&g_bar < (unsigned)gridDim.x) __nanosleep(64);
    }
    __syncthreads();
    __threadfence();

    // ---------------- phase 2: finalize + normalize --------------------------
    if (tid < COUT) {
        float inv_n = 1.0f / (float)NVOX;
        float mean  = g_stats[tid] * inv_n;
        float var   = g_stats[COUT + tid] * inv_n - mean*mean;
        float inv   = rsqrtf(var + 1e-5f);
        float scl   = gamma[tid] * inv;
        sc[tid] = scl;
        sh[tid] = beta[tid] - mean*scl;
    }
    __syncthreads();

    const int total4 = NVOX*COUT/4;           // 2,400,000
    float4* o4 = (float4*)out;
    for (int i = blockIdx.x*blockDim.x + tid; i < total4; i += gridDim.x*blockDim.x) {
        float4 v = o4[i];                      // L2-hot (written in phase 1)
        int bd = (i*4) & (COUT-1);
        v.x = fmaxf(fmaf(v.x, sc[bd+0], sh[bd+0]), 0.f);
        v.y = fmaxf(fmaf(v.y, sc[bd+1], sh[bd+1]), 0.f);
        v.z = fmaxf(fmaf(v.z, sc[bd+2], sh[bd+2]), 0.f);
        v.w = fmaxf(fmaf(v.w, sc[bd+3], sh[bd+3]), 0.f);
        o4[i] = v;
    }

    // ---------------- reset globals for next graph replay --------------------
    __syncthreads();
    if (tid == 0) {
        unsigned d = atomicAdd(&g_done, 1u);
        if (d == (unsigned)gridDim.x - 1u) {
            #pragma unroll
            for (int i = 0; i < 2*COUT; i++) g_stats[i] = 0.f;
            __threadfence();
            g_bar  = 0u;
            g_done = 0u;
            __threadfence();
        }
    }
}

// ---------------------------------------------------------------- launch
extern "C" void kernel_launch(void* const* d_in, const int* in_sizes, int n_in,
                              void* d_out, int out_size)
{
    const float* features = (const float*)d_in[0];  // [150000,32]
    const float* weight   = (const float*)d_in[1];  // [27,32,64]
    const float* gamma    = (const float*)d_in[2];  // [64]
    const float* beta     = (const float*)d_in[3];  // [64]
    const int*   nbr      = (const int*)  d_in[4];  // [27,150000]
    float* out = (float*)d_out;                     // [150000,64]

    fused_kernel<<<NBLK, 32*NWARPS>>>(features, weight, gamma, beta, nbr, out);
}